// round 16
// baseline (speedup 1.0000x reference)
#include <cuda_runtime.h>
#include <cstdint>

#define IN_DIM 1024     // 2*L1
#define LXD    32
#define NBUCK  8
#define MAXB   65536
#define BK     32       // K per pipeline step
#define MTILE  128
#define NTHR   128
#define NSTEP  (IN_DIM / BK)   // 32
#define XSTR   40       // Xs row stride in floats (proven bank pattern)
#define PREPTHR 1024    // prep kernel block size
#define NFRAGBLK 128    // frag-builder blocks (128 * 1024 = 131072 elements)

// ---------------- device scratch ----------------
// Weight fragments: [b][step][split(hi/lo)][kf][nf][lane*2+r] as u32 bf16x2 pairs
__device__ uint32_t g_Wfrag[NBUCK * 32 * 2 * 2 * 4 * 64];   // 1 MB
__device__ int      g_cnt[NBUCK];      // zeroed each replay by a graph memset node
__device__ int      g_list[NBUCK * MAXB];

// ---------------- PTX helpers ----------------
__device__ __forceinline__ unsigned sptr(const void* p) {
    return (unsigned)__cvta_generic_to_shared(p);
}
__device__ __forceinline__ void cp16(void* dst, const void* src) {
    asm volatile("cp.async.cg.shared.global [%0], [%1], 16;\n" :: "r"(sptr(dst)), "l"(src));
}
__device__ __forceinline__ void cp_commit() { asm volatile("cp.async.commit_group;\n"); }
template<int N> __device__ __forceinline__ void cp_wait() {
    asm volatile("cp.async.wait_group %0;\n" :: "n"(N));
}
// pack two f32 -> bf16x2 (upper = hi_src, lower = lo_src)
__device__ __forceinline__ uint32_t cvt_pack(float hi_src, float lo_src) {
    uint32_t r;
    asm("cvt.rn.bf16x2.f32 %0, %1, %2;" : "=r"(r) : "f"(hi_src), "f"(lo_src));
    return r;
}
__device__ __forceinline__ void mma_bf16(float c[4], const uint32_t a[4],
                                         uint32_t b0, uint32_t b1) {
    asm("mma.sync.aligned.m16n8k16.row.col.f32.bf16.bf16.f32 "
        "{%0,%1,%2,%3},{%4,%5,%6,%7},{%8,%9},{%0,%1,%2,%3};"
        : "+f"(c[0]), "+f"(c[1]), "+f"(c[2]), "+f"(c[3])
        : "r"(a[0]), "r"(a[1]), "r"(a[2]), "r"(a[3]), "r"(b0), "r"(b1));
}
// split a float pair (p.x = k, p.y = k+1) into bf16x2 hi + bf16x2 lo
__device__ __forceinline__ void split2(float2 p, uint32_t& h, uint32_t& l) {
    h = cvt_pack(p.y, p.x);
    float e0 = p.x - __uint_as_float(h << 16);
    float e1 = p.y - __uint_as_float(h & 0xffff0000u);
    l = cvt_pack(e1, e0);
}

// ---------------- kernel 1: fused weight-fragment prep + two-level binning ----------------
// Blocks [0, nbin) bin rows (1024 rows each); blocks [nbin, nbin+NFRAGBLK) build fragments.
// g_cnt is zeroed by a memset graph node before this kernel runs.
// ls_indices is int32 on the wire (JAX x64 disabled).
__global__ void __launch_bounds__(PREPTHR)
prep_kernel(const float* __restrict__ w0, const float* __restrict__ w_fact,
            const int* __restrict__ ls, int B, int nbin) {
    const int t = threadIdx.x;

    if (blockIdx.x < nbin) {
        // ---- two-level binning: smem warp counts -> 8 global atomics per CTA ----
        __shared__ int wcnt[32][NBUCK];   // per-warp per-bucket counts
        __shared__ int woff[32][NBUCK];   // exclusive prefix within CTA
        __shared__ int cbase[NBUCK];      // CTA's global base per bucket

        const int w    = t >> 5;
        const int lane = t & 31;
        if (t < 32 * NBUCK) ((int*)wcnt)[t] = 0;
        __syncthreads();

        const int i = blockIdx.x * PREPTHR + t;
        int b = 0, rank = 0;
        const bool valid = (i < B);
        if (valid) {
            b = ls[i] & (NBUCK - 1);
            unsigned m = __match_any_sync(__activemask(), b);
            unsigned below = m & ((1u << lane) - 1u);
            rank = __popc(below);
            if (below == 0) wcnt[w][b] = __popc(m);   // group leader writes count
        }
        __syncthreads();

        if (t < NBUCK) {
            int run = 0;
            for (int ww = 0; ww < 32; ++ww) { woff[ww][t] = run; run += wcnt[ww][t]; }
            cbase[t] = run ? atomicAdd(&g_cnt[t], run) : 0;
        }
        __syncthreads();

        if (valid) {
            int pos = cbase[b] + woff[w][b] + rank;
            g_list[b * MAXB + pos] = i;
        }
    } else {
        // ---- weight fragments: bf16 hi + lo, mma-fragment ordered ----
        int tid = (blockIdx.x - nbin) * PREPTHR + t;   // 0 .. 131071
        if (tid < NBUCK * LXD * 512) {
            int kp = tid & 511;            // k pair index
            int j  = (tid >> 9) & 31;      // output column n
            int b  = tid >> 14;            // bucket
            int k0 = kp * 2;
            float x0 = w0[(b * LXD + j) * IN_DIM + k0]     + w_fact[j * IN_DIM + k0];
            float x1 = w0[(b * LXD + j) * IN_DIM + k0 + 1] + w_fact[j * IN_DIM + k0 + 1];
            uint32_t h, l;
            split2(make_float2(x0, x1), h, l);
            int step = k0 >> 5, kk = k0 & 31;
            int kf = kk >> 4, kr = kk & 15;
            int r = kr >> 3;
            int lane2 = ((j & 7) << 2) + ((kr & 7) >> 1);
            int nf = j >> 3;
            int base = ((((b * 32 + step) * 2 + 0) * 2 + kf) * 4 + nf) * 64 + lane2 * 2 + r;
            g_Wfrag[base]       = h;       // split 0 (hi)
            g_Wfrag[base + 512] = l;       // split 1 (lo), stride 2*4*64
        }
    }

    // PDL: this CTA's dependent writes are done (visibility is flushed at the
    // implicit memory barrier when all CTAs have triggered).
    cudaTriggerProgrammaticLaunchCompletion();
}

// ---------------- kernel 2: tensor-core binned GEMM + fused MLP (champion + PDL) ----------------
struct __align__(16) Smem {
    float    Xs[2][MTILE][XSTR];      // fp32 x tiles (double buffered)  40960 B
    uint32_t Ws[2][1024];             // weight fragments, one K-step (hi+lo)  8192 B
    const float* xptr[MTILE];
    int   perm[MTILE];
    float w1T[LXD * LXD];
    float b0s[LXD], b1s[LXD], w2s[LXD];
    float b2s;
};

__device__ __forceinline__ void process_row(const Smem* S, const float* hrow,
                                            int row, float* __restrict__ out) {
    if (row < 0) return;
    float h2[LXD];
#pragma unroll
    for (int j = 0; j < LXD; ++j) h2[j] = S->b1s[j];
#pragma unroll
    for (int i = 0; i < LXD; ++i) {
        float xi = hrow[i] + S->b0s[i];
        xi = fminf(fmaxf(xi, 0.0f), 1.0f);
        const float* wr = &S->w1T[i * LXD];
#pragma unroll
        for (int j = 0; j < LXD; ++j) h2[j] = fmaf(xi, wr[j], h2[j]);
    }
    float o = S->b2s;
#pragma unroll
    for (int j = 0; j < LXD; ++j) {
        float c = fminf(fmaxf(h2[j], 0.0f), 1.0f);
        o = fmaf(c, S->w2s[j], o);
    }
    out[row] = o;
}

__device__ __forceinline__ void build_a(const float* xp, uint32_t ah[4], uint32_t al[4]) {
    float2 p0 = *reinterpret_cast<const float2*>(xp);                 // row g,   k lo
    float2 p1 = *reinterpret_cast<const float2*>(xp + 8 * XSTR);      // row g+8, k lo
    float2 p2 = *reinterpret_cast<const float2*>(xp + 8);             // row g,   k hi
    float2 p3 = *reinterpret_cast<const float2*>(xp + 8 * XSTR + 8);  // row g+8, k hi
    split2(p0, ah[0], al[0]);
    split2(p1, ah[1], al[1]);
    split2(p2, ah[2], al[2]);
    split2(p3, ah[3], al[3]);
}

__global__ void __launch_bounds__(NTHR, 4)
main_kernel(const float* __restrict__ x,
            const float* __restrict__ b0, const float* __restrict__ b1,
            const float* __restrict__ w1, const float* __restrict__ w2,
            const float* __restrict__ b2,
            float* __restrict__ out, int B) {
    extern __shared__ char smem_raw[];
    Smem* S = reinterpret_cast<Smem*>(smem_raw);

    const int tile = blockIdx.x;
    const int b    = blockIdx.y;
    const int start = tile * MTILE;
    const int t    = threadIdx.x;
    const int lane = t & 31;
    const int warp = t >> 5;
    const int g    = lane >> 2;      // row within 8-group
    const int tq   = lane & 3;       // k quad
    const int wrow = warp * 32;      // warp's 32-row slice (4 warps x 32 = 128)

    // ---- independent prologue: small weights (do NOT depend on prep) ----
    for (int idx = t; idx < LXD * LXD; idx += NTHR) {
        int i = idx >> 5, j = idx & 31;
        S->w1T[idx] = w1[(b * LXD + j) * LXD + i];
    }
    if (t < LXD) {
        S->b0s[t] = b0[b * LXD + t];
        S->b1s[t] = b1[b * LXD + t];
        S->w2s[t] = w2[b * LXD + t];
    }
    if (t == 32) S->b2s = b2[b];

    // ---- PDL: wait for prep's g_cnt/g_list/g_Wfrag to be visible ----
    cudaGridDependencySynchronize();

    const int cnt = g_cnt[b];
    if (start >= cnt) return;

    // ---- prep-dependent metadata ----
    {
        int gi = start + t;
        int ridx = (gi < cnt) ? g_list[b * MAXB + gi] : -1;
        S->perm[t] = ridx;
        S->xptr[t] = x + (size_t)(ridx < 0 ? 0 : ridx) * IN_DIM;
    }
    __syncthreads();

    const uint32_t* wfrag = g_Wfrag + ((size_t)(b * 32) << 10);
    const int k4 = t & 7;        // 8 x 16B chunks cover 128B (BK=32 floats)
    const int rb = t >> 3;       // 16 row-groups

    auto load_step = [&](int stage, int s) {
        int k0 = s * BK;
#pragma unroll
        for (int p = 0; p < MTILE / 16; ++p) {          // 8 rows per thread
            int r = p * 16 + rb;
            cp16(&S->Xs[stage][r][k4 * 4], S->xptr[r] + k0 + k4 * 4);
        }
        const uint32_t* wsrc = wfrag + (s << 10) + t * 8;
        uint32_t* wdst = &S->Ws[stage][t * 8];
        cp16(wdst, wsrc);
        cp16(wdst + 4, wsrc + 4);
        cp_commit();
    };

    float c[2][4][4];
#pragma unroll
    for (int mf = 0; mf < 2; ++mf)
#pragma unroll
        for (int nf = 0; nf < 4; ++nf)
#pragma unroll
            for (int q = 0; q < 4; ++q) c[mf][nf][q] = 0.0f;

    load_step(0, 0);

#pragma unroll 1
    for (int s = 0; s < NSTEP; ++s) {
        const int stage = s & 1;
        if (s + 1 < NSTEP) {
            load_step(stage ^ 1, s + 1);
            cp_wait<1>();
        } else {
            cp_wait<0>();
        }
        __syncthreads();

#pragma unroll
        for (int kf = 0; kf < 2; ++kf) {
            uint32_t ah0[4], al0[4], ah1[4], al1[4];
            build_a(&S->Xs[stage][wrow + g][kf * 16 + 2 * tq], ah0, al0);
            build_a(&S->Xs[stage][wrow + 16 + g][kf * 16 + 2 * tq], ah1, al1);
            const uint32_t* wsb = S->Ws[stage];
#pragma unroll
            for (int nf = 0; nf < 4; ++nf) {
                uint2 bh = *reinterpret_cast<const uint2*>(wsb + (kf * 4 + nf) * 64 + lane * 2);
                uint2 bl = *reinterpret_cast<const uint2*>(wsb + ((2 + kf) * 4 + nf) * 64 + lane * 2);
                mma_bf16(c[0][nf], ah0, bh.x, bh.y);
                mma_bf16(c[0][nf], ah0, bl.x, bl.y);
                mma_bf16(c[0][nf], al0, bh.x, bh.y);
                mma_bf16(c[1][nf], ah1, bh.x, bh.y);
                mma_bf16(c[1][nf], ah1, bl.x, bl.y);
                mma_bf16(c[1][nf], al1, bh.x, bh.y);
            }
        }
        __syncthreads();
    }

    // ---- write layer-0 accumulators to smem (reuse Xs[0]) ----
    float (*Hs)[XSTR] = S->Xs[0];
#pragma unroll
    for (int mf = 0; mf < 2; ++mf)
#pragma unroll
        for (int nf = 0; nf < 4; ++nf) {
            int r0 = wrow + mf * 16 + g;
            int j0 = nf * 8 + 2 * tq;
            *reinterpret_cast<float2*>(&Hs[r0][j0]) =
                make_float2(c[mf][nf][0], c[mf][nf][1]);
            *reinterpret_cast<float2*>(&Hs[r0 + 8][j0]) =
                make_float2(c[mf][nf][2], c[mf][nf][3]);
        }
    __syncthreads();

    // ---- fused layer1 + layer2 epilogue (1 row / thread) ----
    process_row(S, Hs[t], S->perm[t], out);
}

// ---------------- launch ----------------
extern "C" void kernel_launch(void* const* d_in, const int* in_sizes, int n_in,
                              void* d_out, int out_size) {
    const float* x      = (const float*)d_in[0];
    const int*   ls     = (const int*)d_in[1];   // int32 on the wire
    const float* w_fact = (const float*)d_in[2];
    const float* w0     = (const float*)d_in[3];
    const float* b0     = (const float*)d_in[4];
    const float* w1     = (const float*)d_in[5];
    const float* b1     = (const float*)d_in[6];
    const float* w2     = (const float*)d_in[7];
    const float* b2     = (const float*)d_in[8];
    float*       out    = (float*)d_out;

    const int B = in_sizes[0] / IN_DIM;

    // zero bucket counters via a graph-capturable memset node (replay-safe)
    void* cnt_ptr = nullptr;
    cudaGetSymbolAddress(&cnt_ptr, g_cnt);
    cudaMemsetAsync(cnt_ptr, 0, NBUCK * sizeof(int));

    // fused: two-level binning + weight fragments (one launch)
    const int nbin = (B + PREPTHR - 1) / PREPTHR;
    prep_kernel<<<nbin + NFRAGBLK, PREPTHR>>>(w0, w_fact, ls, B, nbin);

    // main kernel with Programmatic Dependent Launch: overlaps its independent
    // prologue (w1/b0/b1/w2/b2 staging) with prep's tail; griddepsync gates
    // the g_cnt/g_list/g_Wfrag reads.
    static const size_t smem_bytes = sizeof(Smem);
    cudaFuncSetAttribute(main_kernel, cudaFuncAttributeMaxDynamicSharedMemorySize,
                         (int)smem_bytes);

    cudaLaunchConfig_t cfg = {};
    cfg.gridDim = dim3((B + MTILE - 1) / MTILE, NBUCK);
    cfg.blockDim = dim3(NTHR);
    cfg.dynamicSmemBytes = smem_bytes;
    cudaLaunchAttribute attrs[1];
    attrs[0].id = cudaLaunchAttributeProgrammaticStreamSerialization;
    attrs[0].val.programmaticStreamSerializationAllowed = 1;
    cfg.attrs = attrs;
    cfg.numAttrs = 1;
    cudaLaunchKernelEx(&cfg, main_kernel, x, b0, b1, w1, w2, b2, out, B);
}

// round 17
// speedup vs baseline: 1.3306x; 1.3306x over previous
#include <cuda_runtime.h>
#include <cstdint>

#define IN_DIM 1024     // 2*L1
#define LXD    32
#define NBUCK  8
#define MAXB   65536
#define BK     32       // K per pipeline step
#define MTILE  128
#define NTHR   128
#define NSTEP  (IN_DIM / BK)   // 32
#define XSTR   40       // Xs row stride in floats (proven bank pattern)
#define PREPTHR 1024    // prep kernel block size
#define NFRAGBLK 128    // frag-builder blocks (128 * 1024 = 131072 elements)

// ---------------- device scratch ----------------
// Weight fragments: [b][step][split(hi/lo)][kf][nf][lane*2+r] as u32 bf16x2 pairs
__device__ uint32_t g_Wfrag[NBUCK * 32 * 2 * 2 * 4 * 64];   // 1 MB
__device__ int      g_cnt[NBUCK];      // zeroed each replay by a graph memset node
__device__ int      g_list[NBUCK * MAXB];

// ---------------- PTX helpers ----------------
__device__ __forceinline__ unsigned sptr(const void* p) {
    return (unsigned)__cvta_generic_to_shared(p);
}
__device__ __forceinline__ void cp16(void* dst, const void* src) {
    asm volatile("cp.async.cg.shared.global [%0], [%1], 16;\n" :: "r"(sptr(dst)), "l"(src));
}
// cp.async with L2 256B sector prefetch: step s's load also pulls step s+1's
// line in the SAME DRAM page visit (rows are 4KB-aligned, steps advance 128B).
__device__ __forceinline__ void cp16_pf256(void* dst, const void* src) {
    asm volatile("cp.async.cg.shared.global.L2::256B [%0], [%1], 16;\n"
                 :: "r"(sptr(dst)), "l"(src));
}
__device__ __forceinline__ void cp_commit() { asm volatile("cp.async.commit_group;\n"); }
template<int N> __device__ __forceinline__ void cp_wait() {
    asm volatile("cp.async.wait_group %0;\n" :: "n"(N));
}
// pack two f32 -> bf16x2 (upper = hi_src, lower = lo_src)
__device__ __forceinline__ uint32_t cvt_pack(float hi_src, float lo_src) {
    uint32_t r;
    asm("cvt.rn.bf16x2.f32 %0, %1, %2;" : "=r"(r) : "f"(hi_src), "f"(lo_src));
    return r;
}
__device__ __forceinline__ void mma_bf16(float c[4], const uint32_t a[4],
                                         uint32_t b0, uint32_t b1) {
    asm("mma.sync.aligned.m16n8k16.row.col.f32.bf16.bf16.f32 "
        "{%0,%1,%2,%3},{%4,%5,%6,%7},{%8,%9},{%0,%1,%2,%3};"
        : "+f"(c[0]), "+f"(c[1]), "+f"(c[2]), "+f"(c[3])
        : "r"(a[0]), "r"(a[1]), "r"(a[2]), "r"(a[3]), "r"(b0), "r"(b1));
}
// split a float pair (p.x = k, p.y = k+1) into bf16x2 hi + bf16x2 lo
__device__ __forceinline__ void split2(float2 p, uint32_t& h, uint32_t& l) {
    h = cvt_pack(p.y, p.x);
    float e0 = p.x - __uint_as_float(h << 16);
    float e1 = p.y - __uint_as_float(h & 0xffff0000u);
    l = cvt_pack(e1, e0);
}

// ---------------- kernel 1: fused weight-fragment prep + two-level binning ----------------
// Blocks [0, nbin) bin rows (1024 rows each); blocks [nbin, nbin+NFRAGBLK) build fragments.
// g_cnt is zeroed by a memset graph node before this kernel runs.
// ls_indices is int32 on the wire (JAX x64 disabled).
__global__ void __launch_bounds__(PREPTHR)
prep_kernel(const float* __restrict__ w0, const float* __restrict__ w_fact,
            const int* __restrict__ ls, int B, int nbin) {
    const int t = threadIdx.x;

    if (blockIdx.x < nbin) {
        // ---- two-level binning: smem warp counts -> 8 global atomics per CTA ----
        __shared__ int wcnt[32][NBUCK];   // per-warp per-bucket counts
        __shared__ int woff[32][NBUCK];   // exclusive prefix within CTA
        __shared__ int cbase[NBUCK];      // CTA's global base per bucket

        const int w    = t >> 5;
        const int lane = t & 31;
        if (t < 32 * NBUCK) ((int*)wcnt)[t] = 0;
        __syncthreads();

        const int i = blockIdx.x * PREPTHR + t;
        int b = 0, rank = 0;
        const bool valid = (i < B);
        if (valid) {
            b = ls[i] & (NBUCK - 1);
            unsigned m = __match_any_sync(__activemask(), b);
            unsigned below = m & ((1u << lane) - 1u);
            rank = __popc(below);
            if (below == 0) wcnt[w][b] = __popc(m);   // group leader writes count
        }
        __syncthreads();

        if (t < NBUCK) {
            int run = 0;
            for (int ww = 0; ww < 32; ++ww) { woff[ww][t] = run; run += wcnt[ww][t]; }
            cbase[t] = run ? atomicAdd(&g_cnt[t], run) : 0;
        }
        __syncthreads();

        if (valid) {
            int pos = cbase[b] + woff[w][b] + rank;
            g_list[b * MAXB + pos] = i;
        }
    } else {
        // ---- weight fragments: bf16 hi + lo, mma-fragment ordered ----
        int tid = (blockIdx.x - nbin) * PREPTHR + t;   // 0 .. 131071
        if (tid < NBUCK * LXD * 512) {
            int kp = tid & 511;            // k pair index
            int j  = (tid >> 9) & 31;      // output column n
            int b  = tid >> 14;            // bucket
            int k0 = kp * 2;
            float x0 = w0[(b * LXD + j) * IN_DIM + k0]     + w_fact[j * IN_DIM + k0];
            float x1 = w0[(b * LXD + j) * IN_DIM + k0 + 1] + w_fact[j * IN_DIM + k0 + 1];
            uint32_t h, l;
            split2(make_float2(x0, x1), h, l);
            int step = k0 >> 5, kk = k0 & 31;
            int kf = kk >> 4, kr = kk & 15;
            int r = kr >> 3;
            int lane2 = ((j & 7) << 2) + ((kr & 7) >> 1);
            int nf = j >> 3;
            int base = ((((b * 32 + step) * 2 + 0) * 2 + kf) * 4 + nf) * 64 + lane2 * 2 + r;
            g_Wfrag[base]       = h;       // split 0 (hi)
            g_Wfrag[base + 512] = l;       // split 1 (lo), stride 2*4*64
        }
    }
}

// ---------------- kernel 2: tensor-core binned GEMM + fused MLP (champion) ----------------
struct __align__(16) Smem {
    float    Xs[2][MTILE][XSTR];      // fp32 x tiles (double buffered)  40960 B
    uint32_t Ws[2][1024];             // weight fragments, one K-step (hi+lo)  8192 B
    const float* xptr[MTILE];
    int   perm[MTILE];
    float w1T[LXD * LXD];
    float b0s[LXD], b1s[LXD], w2s[LXD];
    float b2s;
};

__device__ __forceinline__ void process_row(const Smem* S, const float* hrow,
                                            int row, float* __restrict__ out) {
    if (row < 0) return;
    float h2[LXD];
#pragma unroll
    for (int j = 0; j < LXD; ++j) h2[j] = S->b1s[j];
#pragma unroll
    for (int i = 0; i < LXD; ++i) {
        float xi = hrow[i] + S->b0s[i];
        xi = fminf(fmaxf(xi, 0.0f), 1.0f);
        const float* wr = &S->w1T[i * LXD];
#pragma unroll
        for (int j = 0; j < LXD; ++j) h2[j] = fmaf(xi, wr[j], h2[j]);
    }
    float o = S->b2s;
#pragma unroll
    for (int j = 0; j < LXD; ++j) {
        float c = fminf(fmaxf(h2[j], 0.0f), 1.0f);
        o = fmaf(c, S->w2s[j], o);
    }
    out[row] = o;
}

__device__ __forceinline__ void build_a(const float* xp, uint32_t ah[4], uint32_t al[4]) {
    float2 p0 = *reinterpret_cast<const float2*>(xp);                 // row g,   k lo
    float2 p1 = *reinterpret_cast<const float2*>(xp + 8 * XSTR);      // row g+8, k lo
    float2 p2 = *reinterpret_cast<const float2*>(xp + 8);             // row g,   k hi
    float2 p3 = *reinterpret_cast<const float2*>(xp + 8 * XSTR + 8);  // row g+8, k hi
    split2(p0, ah[0], al[0]);
    split2(p1, ah[1], al[1]);
    split2(p2, ah[2], al[2]);
    split2(p3, ah[3], al[3]);
}

__global__ void __launch_bounds__(NTHR, 4)
main_kernel(const float* __restrict__ x,
            const float* __restrict__ b0, const float* __restrict__ b1,
            const float* __restrict__ w1, const float* __restrict__ w2,
            const float* __restrict__ b2,
            float* __restrict__ out, int B) {
    extern __shared__ char smem_raw[];
    Smem* S = reinterpret_cast<Smem*>(smem_raw);

    const int tile = blockIdx.x;
    const int b    = blockIdx.y;
    const int cnt  = g_cnt[b];
    const int start = tile * MTILE;
    if (start >= cnt) return;

    const int t    = threadIdx.x;
    const int lane = t & 31;
    const int warp = t >> 5;
    const int g    = lane >> 2;      // row within 8-group
    const int tq   = lane & 3;       // k quad
    const int wrow = warp * 32;      // warp's 32-row slice (4 warps x 32 = 128)

    // ---- stage per-CTA metadata + small weights ----
    {
        int gi = start + t;
        int ridx = (gi < cnt) ? g_list[b * MAXB + gi] : -1;
        S->perm[t] = ridx;
        S->xptr[t] = x + (size_t)(ridx < 0 ? 0 : ridx) * IN_DIM;
    }
    for (int idx = t; idx < LXD * LXD; idx += NTHR) {
        int i = idx >> 5, j = idx & 31;
        S->w1T[idx] = w1[(b * LXD + j) * LXD + i];
    }
    if (t < LXD) {
        S->b0s[t] = b0[b * LXD + t];
        S->b1s[t] = b1[b * LXD + t];
        S->w2s[t] = w2[b * LXD + t];
    }
    if (t == 32) S->b2s = b2[b];
    __syncthreads();

    const uint32_t* wfrag = g_Wfrag + ((size_t)(b * 32) << 10);
    const int k4 = t & 7;        // 8 x 16B chunks cover 128B (BK=32 floats)
    const int rb = t >> 3;       // 16 row-groups

    auto load_step = [&](int stage, int s) {
        int k0 = s * BK;
#pragma unroll
        for (int p = 0; p < MTILE / 16; ++p) {          // 8 rows per thread
            int r = p * 16 + rb;
            cp16_pf256(&S->Xs[stage][r][k4 * 4], S->xptr[r] + k0 + k4 * 4);
        }
        const uint32_t* wsrc = wfrag + (s << 10) + t * 8;
        uint32_t* wdst = &S->Ws[stage][t * 8];
        cp16(wdst, wsrc);
        cp16(wdst + 4, wsrc + 4);
        cp_commit();
    };

    float c[2][4][4];
#pragma unroll
    for (int mf = 0; mf < 2; ++mf)
#pragma unroll
        for (int nf = 0; nf < 4; ++nf)
#pragma unroll
            for (int q = 0; q < 4; ++q) c[mf][nf][q] = 0.0f;

    load_step(0, 0);

#pragma unroll 1
    for (int s = 0; s < NSTEP; ++s) {
        const int stage = s & 1;
        if (s + 1 < NSTEP) {
            load_step(stage ^ 1, s + 1);
            cp_wait<1>();
        } else {
            cp_wait<0>();
        }
        __syncthreads();

#pragma unroll
        for (int kf = 0; kf < 2; ++kf) {
            uint32_t ah0[4], al0[4], ah1[4], al1[4];
            build_a(&S->Xs[stage][wrow + g][kf * 16 + 2 * tq], ah0, al0);
            build_a(&S->Xs[stage][wrow + 16 + g][kf * 16 + 2 * tq], ah1, al1);
            const uint32_t* wsb = S->Ws[stage];
#pragma unroll
            for (int nf = 0; nf < 4; ++nf) {
                uint2 bh = *reinterpret_cast<const uint2*>(wsb + (kf * 4 + nf) * 64 + lane * 2);
                uint2 bl = *reinterpret_cast<const uint2*>(wsb + ((2 + kf) * 4 + nf) * 64 + lane * 2);
                mma_bf16(c[0][nf], ah0, bh.x, bh.y);
                mma_bf16(c[0][nf], ah0, bl.x, bl.y);
                mma_bf16(c[0][nf], al0, bh.x, bh.y);
                mma_bf16(c[1][nf], ah1, bh.x, bh.y);
                mma_bf16(c[1][nf], ah1, bl.x, bl.y);
                mma_bf16(c[1][nf], al1, bh.x, bh.y);
            }
        }
        __syncthreads();
    }

    // ---- write layer-0 accumulators to smem (reuse Xs[0]) ----
    float (*Hs)[XSTR] = S->Xs[0];
#pragma unroll
    for (int mf = 0; mf < 2; ++mf)
#pragma unroll
        for (int nf = 0; nf < 4; ++nf) {
            int r0 = wrow + mf * 16 + g;
            int j0 = nf * 8 + 2 * tq;
            *reinterpret_cast<float2*>(&Hs[r0][j0]) =
                make_float2(c[mf][nf][0], c[mf][nf][1]);
            *reinterpret_cast<float2*>(&Hs[r0 + 8][j0]) =
                make_float2(c[mf][nf][2], c[mf][nf][3]);
        }
    __syncthreads();

    // ---- fused layer1 + layer2 epilogue (1 row / thread) ----
    process_row(S, Hs[t], S->perm[t], out);
}

// ---------------- launch ----------------
extern "C" void kernel_launch(void* const* d_in, const int* in_sizes, int n_in,
                              void* d_out, int out_size) {
    const float* x      = (const float*)d_in[0];
    const int*   ls     = (const int*)d_in[1];   // int32 on the wire
    const float* w_fact = (const float*)d_in[2];
    const float* w0     = (const float*)d_in[3];
    const float* b0     = (const float*)d_in[4];
    const float* w1     = (const float*)d_in[5];
    const float* b1     = (const float*)d_in[6];
    const float* w2     = (const float*)d_in[7];
    const float* b2     = (const float*)d_in[8];
    float*       out    = (float*)d_out;

    const int B = in_sizes[0] / IN_DIM;

    // zero bucket counters via a graph-capturable memset node (replay-safe)
    void* cnt_ptr = nullptr;
    cudaGetSymbolAddress(&cnt_ptr, g_cnt);
    cudaMemsetAsync(cnt_ptr, 0, NBUCK * sizeof(int));

    // fused: two-level binning + weight fragments (one launch)
    const int nbin = (B + PREPTHR - 1) / PREPTHR;
    prep_kernel<<<nbin + NFRAGBLK, PREPTHR>>>(w0, w_fact, ls, B, nbin);

    static const size_t smem_bytes = sizeof(Smem);
    cudaFuncSetAttribute(main_kernel, cudaFuncAttributeMaxDynamicSharedMemorySize,
                         (int)smem_bytes);
    dim3 grid((B + MTILE - 1) / MTILE, NBUCK);
    main_kernel<<<grid, NTHR, smem_bytes>>>(x, b0, b1, w1, w2, b2, out, B);
}